// round 1
// baseline (speedup 1.0000x reference)
#include <cuda_runtime.h>
#include <math.h>

#define Nn 100000
#define Ee 3200000
#define Ff 128
#define Hh 16
#define Cc 10
#define Kk1 25000
#define Kk2 6250

// ---------------- scratch (device globals; no runtime allocation) -------------
__device__ float d_h0[Nn * Hh];          // x @ W1
__device__ float d_h[Nn * Hh];           // conv1 agg -> relu(h)
__device__ float d_dinv[Nn];             // deg accumulator -> 1/sqrt(deg+1)
__device__ float d_t[Nn];                // h @ wrel
__device__ float d_score[Nn];            // pool1 scores
__device__ unsigned long long d_key[Nn]; // radix-select keys (reused for pool2)
__device__ int d_perm[Kk1];              // selected node ids (reused for pool2)
__device__ int d_newidx[Nn];             // old -> new relabel
__device__ unsigned int d_epack[Ee];     // packed relabeled edges: ns|nd<<15|valid<<31
__device__ float d_x1[Kk1 * Hh];         // pooled features after pool1
__device__ float d_g0[Kk1 * Cc];         // x1 @ W2
__device__ float d_h2[Kk1 * Cc];         // conv2 output
__device__ float d_dinv2[Kk1];
__device__ float d_t2[Kk1];
__device__ float d_score2[Kk1];
__device__ unsigned int d_hist[256];
__device__ unsigned long long d_prefix;
__device__ int d_remk;
__device__ int d_counter;

// ---------------- init -------------------------------------------------------
__global__ void k_init() {
    int i = blockIdx.x * blockDim.x + threadIdx.x;
    if (i < Nn) { d_dinv[i] = 0.f; d_newidx[i] = -1; }
    if (i < Kk1) d_dinv2[i] = 0.f;
}

// ---------------- conv1: h0 = x @ W1 (warp per node) --------------------------
__global__ void k_mm1(const float* __restrict__ x, const float* __restrict__ W1) {
    __shared__ float Ws[Ff * Hh];
    for (int i = threadIdx.x; i < Ff * Hh; i += blockDim.x) Ws[i] = W1[i];
    __syncthreads();
    int gwarp = (blockIdx.x * blockDim.x + threadIdx.x) >> 5;
    int lane = threadIdx.x & 31;
    if (gwarp >= Nn) return;
    const float* xr = x + (size_t)gwarp * Ff;
    float acc[Hh];
#pragma unroll
    for (int j = 0; j < Hh; j++) acc[j] = 0.f;
#pragma unroll
    for (int c = 0; c < 4; c++) {
        int f = c * 32 + lane;
        float xv = xr[f];
        const float* wr = Ws + f * Hh;
#pragma unroll
        for (int j = 0; j < Hh; j++) acc[j] += xv * wr[j];
    }
#pragma unroll
    for (int off = 16; off; off >>= 1)
#pragma unroll
        for (int j = 0; j < Hh; j++) acc[j] += __shfl_xor_sync(0xFFFFFFFFu, acc[j], off);
    if (lane < Hh) d_h0[(size_t)gwarp * Hh + lane] = acc[lane];
}

// degree: deg[dst] += 1
__global__ void k_deg(const int* __restrict__ dst) {
    int e = blockIdx.x * blockDim.x + threadIdx.x;
    if (e < Ee) atomicAdd(&d_dinv[dst[e]], 1.0f);
}
__global__ void k_rsqrt1() {
    int i = blockIdx.x * blockDim.x + threadIdx.x;
    if (i < Nn) d_dinv[i] = rsqrtf(d_dinv[i] + 1.0f);
}
// agg init: self-loop message + bias
__global__ void k_initagg1(const float* __restrict__ b1) {
    int i = blockIdx.x * blockDim.x + threadIdx.x;
    if (i >= Nn * Hh) return;
    int node = i >> 4, j = i & 15;
    float di = d_dinv[node];
    d_h[i] = d_h0[i] * di * di + b1[j];
}
// edge scatter: 16 threads per edge
__global__ void k_scat1(const int* __restrict__ src, const int* __restrict__ dst) {
    int t = blockIdx.x * blockDim.x + threadIdx.x;
    int e = t >> 4, j = t & 15;
    if (e >= Ee) return;
    int s = src[e], d = dst[e];
    float nrm = d_dinv[s] * d_dinv[d];
    atomicAdd(&d_h[d * Hh + j], d_h0[s * Hh + j] * nrm);
}
// relu in place + score prep (wroot/wrel dots)
__global__ void k_prep1(const float* __restrict__ wroot, const float* __restrict__ wrel,
                        const float* __restrict__ pb) {
    int i = blockIdx.x * blockDim.x + threadIdx.x;
    if (i >= Nn) return;
    float sr = 0.f, st = 0.f;
#pragma unroll
    for (int j = 0; j < Hh; j++) {
        float v = fmaxf(d_h[i * Hh + j], 0.f);
        d_h[i * Hh + j] = v;
        sr += v * __ldg(&wroot[j]);
        st += v * __ldg(&wrel[j]);
    }
    d_score[i] = sr + __ldg(&pb[0]);
    d_t[i] = st;
}
__global__ void k_scats1(const int* __restrict__ src, const int* __restrict__ dst) {
    int e = blockIdx.x * blockDim.x + threadIdx.x;
    if (e < Ee) atomicAdd(&d_score[dst[e]], d_t[src[e]]);
}

// ---------------- radix select (top-k over 64-bit composite key) -------------
__device__ __forceinline__ unsigned f2u(float f) {
    unsigned u = __float_as_uint(f);
    return (u & 0x80000000u) ? ~u : (u | 0x80000000u);
}
__global__ void k_keys1() {
    int i = blockIdx.x * blockDim.x + threadIdx.x;
    if (i >= Nn) return;
    d_key[i] = ((unsigned long long)f2u(d_score[i]) << 32) |
               (unsigned long long)(0xFFFFFFFFu - (unsigned)i);
}
__global__ void k_keys2() {
    int i = blockIdx.x * blockDim.x + threadIdx.x;
    if (i >= Kk1) return;
    d_key[i] = ((unsigned long long)f2u(d_score2[i]) << 32) |
               (unsigned long long)(0xFFFFFFFFu - (unsigned)i);
}
__global__ void k_reset(int k) {
    d_hist[threadIdx.x] = 0;
    if (threadIdx.x == 0) { d_prefix = 0ull; d_remk = k; d_counter = 0; }
}
__global__ void k_hist(int n, int shift) {
    __shared__ unsigned sh[256];
    sh[threadIdx.x] = 0;
    __syncthreads();
    unsigned long long pre = d_prefix;
    for (int i = blockIdx.x * blockDim.x + threadIdx.x; i < n; i += gridDim.x * blockDim.x) {
        unsigned long long k = d_key[i];
        bool ok = (shift >= 56) || ((k >> (shift + 8)) == pre);
        if (ok) atomicAdd(&sh[(unsigned)(k >> shift) & 255u], 1u);
    }
    __syncthreads();
    if (sh[threadIdx.x]) atomicAdd(&d_hist[threadIdx.x], sh[threadIdx.x]);
}
__global__ void k_scan() {
    __shared__ unsigned sh[256];
    sh[threadIdx.x] = d_hist[threadIdx.x];
    __syncthreads();
    if (threadIdx.x == 0) {
        int rem = d_remk;
        unsigned cum = 0;
        for (int v = 255; v >= 0; v--) {
            unsigned c = sh[v];
            cum += c;
            if ((int)cum >= rem) {
                d_prefix = (d_prefix << 8) | (unsigned long long)v;
                d_remk = rem - (int)(cum - c);
                break;
            }
        }
    }
    __syncthreads();
    d_hist[threadIdx.x] = 0;
}
__global__ void k_select(int n) {
    int i = blockIdx.x * blockDim.x + threadIdx.x;
    if (i >= n) return;
    if (d_key[i] >= d_prefix) {
        int p = atomicAdd(&d_counter, 1);
        d_perm[p] = i;
    }
}

// ---------------- pool1 outputs ----------------------------------------------
__global__ void k_setperm() {
    int p = blockIdx.x * blockDim.x + threadIdx.x;
    if (p < Kk1) d_newidx[d_perm[p]] = p;
}
__global__ void k_gather1() {
    int p = blockIdx.x * blockDim.x + threadIdx.x;
    if (p >= Kk1) return;
    int i = d_perm[p];
    float th = tanhf(d_score[i]);
#pragma unroll
    for (int j = 0; j < Hh; j++) d_x1[p * Hh + j] = d_h[i * Hh + j] * th;
}
__global__ void k_relabel(const int* __restrict__ src, const int* __restrict__ dst) {
    int e = blockIdx.x * blockDim.x + threadIdx.x;
    if (e >= Ee) return;
    int ns = d_newidx[src[e]], nd = d_newidx[dst[e]];
    unsigned pk = 0;
    if (ns >= 0 && nd >= 0) {
        pk = (unsigned)ns | ((unsigned)nd << 15) | 0x80000000u;
        atomicAdd(&d_dinv2[nd], 1.0f);
    }
    d_epack[e] = pk;
}

// ---------------- conv2 -------------------------------------------------------
__global__ void k_rsqrt2() {
    int i = blockIdx.x * blockDim.x + threadIdx.x;
    if (i < Kk1) d_dinv2[i] = rsqrtf(d_dinv2[i] + 1.0f);
}
__global__ void k_mm2(const float* __restrict__ W2) {
    int i = blockIdx.x * blockDim.x + threadIdx.x;
    if (i >= Kk1) return;
    float xr[Hh];
#pragma unroll
    for (int f = 0; f < Hh; f++) xr[f] = d_x1[i * Hh + f];
#pragma unroll
    for (int j = 0; j < Cc; j++) {
        float a = 0.f;
#pragma unroll
        for (int f = 0; f < Hh; f++) a += xr[f] * __ldg(&W2[f * Cc + j]);
        d_g0[i * Cc + j] = a;
    }
}
__global__ void k_initagg2(const float* __restrict__ b2) {
    int i = blockIdx.x * blockDim.x + threadIdx.x;
    if (i >= Kk1) return;
    float di = d_dinv2[i];
    di *= di;
#pragma unroll
    for (int j = 0; j < Cc; j++) d_h2[i * Cc + j] = d_g0[i * Cc + j] * di + __ldg(&b2[j]);
}
__global__ void k_scat2() {
    int e = blockIdx.x * blockDim.x + threadIdx.x;
    if (e >= Ee) return;
    unsigned pk = d_epack[e];
    if (!(pk >> 31)) return;
    int ns = pk & 32767, nd = (pk >> 15) & 32767;
    float nrm = d_dinv2[ns] * d_dinv2[nd];
    const float* g = &d_g0[ns * Cc];
    float* a = &d_h2[nd * Cc];
#pragma unroll
    for (int j = 0; j < Cc; j++) atomicAdd(&a[j], g[j] * nrm);
}
__global__ void k_prep2(const float* __restrict__ wroot, const float* __restrict__ wrel,
                        const float* __restrict__ pb) {
    int i = blockIdx.x * blockDim.x + threadIdx.x;
    if (i >= Kk1) return;
    float sr = 0.f, st = 0.f;
#pragma unroll
    for (int j = 0; j < Cc; j++) {
        float v = d_h2[i * Cc + j];
        sr += v * __ldg(&wroot[j]);
        st += v * __ldg(&wrel[j]);
    }
    d_score2[i] = sr + __ldg(&pb[0]);
    d_t2[i] = st;
}
__global__ void k_scats2() {
    int e = blockIdx.x * blockDim.x + threadIdx.x;
    if (e >= Ee) return;
    unsigned pk = d_epack[e];
    if (!(pk >> 31)) return;
    int ns = pk & 32767, nd = (pk >> 15) & 32767;
    atomicAdd(&d_score2[nd], d_t2[ns]);
}

// ---------------- final: mean over selected, log_softmax ----------------------
__global__ void k_reduce(float* __restrict__ out) {
    float acc[Cc];
#pragma unroll
    for (int j = 0; j < Cc; j++) acc[j] = 0.f;
    for (int p = threadIdx.x; p < Kk2; p += 256) {
        int i = d_perm[p];
        float th = tanhf(d_score2[i]);
#pragma unroll
        for (int j = 0; j < Cc; j++) acc[j] += d_h2[i * Cc + j] * th;
    }
#pragma unroll
    for (int off = 16; off; off >>= 1)
#pragma unroll
        for (int j = 0; j < Cc; j++) acc[j] += __shfl_xor_sync(0xFFFFFFFFu, acc[j], off);
    __shared__ float sh[8][Cc];
    int w = threadIdx.x >> 5, l = threadIdx.x & 31;
    if (l == 0)
#pragma unroll
        for (int j = 0; j < Cc; j++) sh[w][j] = acc[j];
    __syncthreads();
    if (threadIdx.x == 0) {
        float m[Cc], mx = -1e30f;
#pragma unroll
        for (int j = 0; j < Cc; j++) {
            float s = 0.f;
            for (int ww = 0; ww < 8; ww++) s += sh[ww][j];
            m[j] = s / (float)Kk2;
            mx = fmaxf(mx, m[j]);
        }
        float lse = 0.f;
#pragma unroll
        for (int j = 0; j < Cc; j++) lse += expf(m[j] - mx);
        lse = logf(lse);
#pragma unroll
        for (int j = 0; j < Cc; j++) out[j] = m[j] - mx - lse;
    }
}

// ---------------- launch ------------------------------------------------------
extern "C" void kernel_launch(void* const* d_in, const int* in_sizes, int n_in,
                              void* d_out, int out_size) {
    const float* x = (const float*)d_in[0];
    const int* esrc = (const int*)d_in[1];
    const int* edst = (const int*)d_in[2];
    const float* W1 = (const float*)d_in[3];
    const float* b1 = (const float*)d_in[4];
    const float* p1wr = (const float*)d_in[5];
    const float* p1wl = (const float*)d_in[6];
    const float* p1b = (const float*)d_in[7];
    const float* W2 = (const float*)d_in[8];
    const float* b2 = (const float*)d_in[9];
    const float* p2wr = (const float*)d_in[10];
    const float* p2wl = (const float*)d_in[11];
    const float* p2b = (const float*)d_in[12];
    float* out = (float*)d_out;

    const int T = 256;
    k_init<<<(Nn + T - 1) / T, T>>>();
    k_mm1<<<Nn / 4, 128>>>(x, W1);
    k_deg<<<(Ee + T - 1) / T, T>>>(edst);
    k_rsqrt1<<<(Nn + T - 1) / T, T>>>();
    k_initagg1<<<(Nn * Hh + T - 1) / T, T>>>(b1);
    k_scat1<<<(Ee * 16 + T - 1) / T, T>>>(esrc, edst);
    k_prep1<<<(Nn + T - 1) / T, T>>>(p1wr, p1wl, p1b);
    k_scats1<<<(Ee + T - 1) / T, T>>>(esrc, edst);

    k_keys1<<<(Nn + T - 1) / T, T>>>();
    k_reset<<<1, 256>>>(Kk1);
    for (int s = 56; s >= 0; s -= 8) {
        k_hist<<<160, 256>>>(Nn, s);
        k_scan<<<1, 256>>>();
    }
    k_select<<<(Nn + T - 1) / T, T>>>(Nn);
    k_setperm<<<(Kk1 + T - 1) / T, T>>>();
    k_gather1<<<(Kk1 + T - 1) / T, T>>>();
    k_relabel<<<(Ee + T - 1) / T, T>>>(esrc, edst);

    k_rsqrt2<<<(Kk1 + T - 1) / T, T>>>();
    k_mm2<<<(Kk1 + T - 1) / T, T>>>(W2);
    k_initagg2<<<(Kk1 + T - 1) / T, T>>>(b2);
    k_scat2<<<(Ee + T - 1) / T, T>>>();
    k_prep2<<<(Kk1 + T - 1) / T, T>>>(p2wr, p2wl, p2b);
    k_scats2<<<(Ee + T - 1) / T, T>>>();

    k_keys2<<<(Kk1 + T - 1) / T, T>>>();
    k_reset<<<1, 256>>>(Kk2);
    for (int s = 56; s >= 0; s -= 8) {
        k_hist<<<160, 256>>>(Kk1, s);
        k_scan<<<1, 256>>>();
    }
    k_select<<<(Kk1 + T - 1) / T, T>>>(Kk1);

    k_reduce<<<1, 256>>>(out);
}